// round 9
// baseline (speedup 1.0000x reference)
#include <cuda_runtime.h>

// ---------------------------------------------------------------------------
// EdgeAttrConstruct: out[e] = L(L(L((x[s]+x[d])@W0+b0)@W1+b1)@W2+b2), L=leaky(0.05)
// Factored: h0 = x@W0 per node; per edge: act1 = L(h0[s]+h0[d]+b0), then two
// TF32 mma GEMMs per 128-edge tile. Fragment operands live in a PERMUTED-K
// smem layout, P(k) = (k&3)*36 + (k>>2), so each thread's mma fragment stream
// is contiguous -> LDS.128 loads fragments for TWO k-chunks at once (4x fewer
// shared-load instructions vs scalar fragment loads).
// edge_index is int32 (JAX canonicalization).
// ---------------------------------------------------------------------------

#define SLOPE 0.05f

constexpr int ND = 64;
constexpr int HD = 128;
constexpr int OD = 64;

constexpr int TILE_E = 128;          // edges per tile (32 per band)
constexpr int RS = 144;              // row stride (floats): 4 c-blocks * 36, ==16 mod 32
constexpr int NACTP = TILE_E * RS;   // 18432 floats
constexpr int NW1T  = HD * RS;       // 18432 floats (W1 transposed, n-major)
constexpr int NW2T  = OD * RS;       //  9216 floats (W2 transposed, n-major)
constexpr int SMEM_FLOATS = NACTP + NW1T + NW2T + 128 + 128 + 64;
constexpr int SMEM_BYTES = SMEM_FLOATS * 4;   // 185600 B

__device__ float g_h0[(size_t)50000 * HD];

__device__ __forceinline__ float leaky(float v) { return v >= 0.f ? v : SLOPE * v; }

__device__ __forceinline__ unsigned tf32u(float x) {
    unsigned u;
    asm("cvt.rna.tf32.f32 %0, %1;" : "=r"(u) : "f"(x));
    return u;
}
__device__ __forceinline__ float tf32f(float x) { return __uint_as_float(tf32u(x)); }

__device__ __forceinline__ int permk(int k) { return (k & 3) * 36 + (k >> 2); }

__device__ __forceinline__ void mma_tf32(float* c, unsigned a0, unsigned a1,
                                         unsigned a2, unsigned a3,
                                         unsigned b0, unsigned b1) {
    asm volatile(
        "mma.sync.aligned.m16n8k8.row.col.f32.tf32.tf32.f32 "
        "{%0,%1,%2,%3}, {%4,%5,%6,%7}, {%8,%9}, {%0,%1,%2,%3};"
        : "+f"(c[0]), "+f"(c[1]), "+f"(c[2]), "+f"(c[3])
        : "r"(a0), "r"(a1), "r"(a2), "r"(a3), "r"(b0), "r"(b1));
}

__device__ __forceinline__ void band_bar(int band) {
    asm volatile("bar.sync %0, 128;" :: "r"(band + 1) : "memory");
}

// ---------------------------------------------------------------------------
// Kernel 1: g_h0 = x @ W0   (50000x64 @ 64x128)
// ---------------------------------------------------------------------------
__global__ __launch_bounds__(256) void node_gemm(
    const float* __restrict__ x, const float* __restrict__ W0, int n_nodes)
{
    __shared__ float sW[ND * HD];
    __shared__ float sX[64 * 68];

    const int tid = threadIdx.x;
    for (int i = tid; i < ND * HD; i += 256) sW[i] = W0[i];

    const int node0 = blockIdx.x * 64;
    for (int t = tid; t < 64 * 16; t += 256) {
        int r = t >> 4, q = t & 15;
        int node = node0 + r;
        float4 v = make_float4(0.f, 0.f, 0.f, 0.f);
        if (node < n_nodes) v = *reinterpret_cast<const float4*>(x + (size_t)node * ND + q * 4);
        *reinterpret_cast<float4*>(sX + r * 68 + q * 4) = v;
    }
    __syncthreads();

    const int tx = tid & 31, ty = tid >> 5;
    float acc[8][4];
#pragma unroll
    for (int i = 0; i < 8; i++)
#pragma unroll
        for (int j = 0; j < 4; j++) acc[i][j] = 0.f;

#pragma unroll 4
    for (int k = 0; k < ND; k++) {
        float w[4];
#pragma unroll
        for (int j = 0; j < 4; j++) w[j] = sW[k * HD + tx + 32 * j];
#pragma unroll
        for (int i = 0; i < 8; i++) {
            float xv = sX[(ty + 8 * i) * 68 + k];
#pragma unroll
            for (int j = 0; j < 4; j++) acc[i][j] = fmaf(xv, w[j], acc[i][j]);
        }
    }

#pragma unroll
    for (int i = 0; i < 8; i++) {
        int node = node0 + ty + 8 * i;
        if (node < n_nodes) {
#pragma unroll
            for (int j = 0; j < 4; j++)
                g_h0[(size_t)node * HD + tx + 32 * j] = acc[i][j];
        }
    }
}

// ---------------------------------------------------------------------------
// Kernel 2: persistent edge MLP. grid=148, 512 threads, 185.6 KB dyn smem.
// 4 bands x 4 warps (named barriers). Permuted-k fragment layout throughout.
// ---------------------------------------------------------------------------
__global__ __launch_bounds__(512, 1) void edge_mlp(
    const int* __restrict__ ei,
    const float* __restrict__ W1, const float* __restrict__ W2,
    const float* __restrict__ b0, const float* __restrict__ b1,
    const float* __restrict__ b2,
    float* __restrict__ out, int n_edges, int n_nodes)
{
    extern __shared__ float sm[];
    float* sAct = sm;                 // [128][RS]  activations, permuted-k
    float* sW1T = sAct + NACTP;       // [128][RS]  W1T[n][P(k)] = tf32(W1[k][n])
    float* sW2T = sW1T + NW1T;        // [64][RS]   W2T[n][P(k)] = tf32(W2[k][n])
    float* sB0 = sW2T + NW2T;         // [128]
    float* sB1 = sB0 + 128;           // [128]
    float* sB2 = sB1 + 128;           // [64]

    const int tid = threadIdx.x;

    // one-time weight staging into transposed + permuted layout
    for (int i = tid; i < HD * HD; i += 512) {
        int n = i & 127, k = i >> 7;
        sW1T[n * RS + permk(k)] = tf32f(W1[k * HD + n]);
    }
    for (int i = tid; i < HD * OD; i += 512) {
        int n = i & 63, k = i >> 6;
        sW2T[n * RS + permk(k)] = tf32f(W2[k * OD + n]);
    }
    if (tid < 128) { sB0[tid] = b0[tid]; sB1[tid] = b1[tid]; }
    else if (tid >= 256 && tid < 320) sB2[tid - 256] = b2[tid - 256];
    __syncthreads();

    const int lane = tid & 31, wid = tid >> 5;
    const int g = lane >> 2, c = lane & 3;
    const int band = wid & 3;         // 32-row band, 4 warps each
    const int sub  = wid >> 2;
    const int m0  = band * 32;
    const int n0  = sub * 32;         // GEMM1 n-tile base
    const int n02 = sub * 16;         // GEMM2 n-tile base
    const int cb  = c * 36;           // c-block offset in permuted layout

    const int n_tiles = (n_edges + TILE_E - 1) / TILE_E;
    for (int tile = blockIdx.x; tile < n_tiles; tile += gridDim.x) {
        const int e0 = tile * TILE_E;

        // ---- gather: warp owns 8 rows [m0+sub*8, +8); permuted scalar STS ----
        {
            const int e_base = e0 + m0 + sub * 8;
            int idx = 0;
            if (lane < 16) {
                int e = e_base + (lane & 7);
                if (e < n_edges)
                    idx = __ldg(ei + (lane < 8 ? 0 : (size_t)n_edges) + e);
            }
            idx = min(max(idx, 0), n_nodes - 1);
            float4 bb = *reinterpret_cast<const float4*>(sB0 + lane * 4);
#pragma unroll
            for (int i = 0; i < 8; i++) {
                int s = __shfl_sync(0xffffffffu, idx, i);
                int d = __shfl_sync(0xffffffffu, idx, i + 8);
                float4 w;
                if (e_base + i < n_edges) {
                    float4 va = *reinterpret_cast<const float4*>(&g_h0[(size_t)s * HD + lane * 4]);
                    float4 vb = *reinterpret_cast<const float4*>(&g_h0[(size_t)d * HD + lane * 4]);
                    w.x = tf32f(leaky(va.x + vb.x + bb.x));
                    w.y = tf32f(leaky(va.y + vb.y + bb.y));
                    w.z = tf32f(leaky(va.z + vb.z + bb.z));
                    w.w = tf32f(leaky(va.w + vb.w + bb.w));
                } else {
                    w = make_float4(0.f, 0.f, 0.f, 0.f);
                }
                // k = 4*lane + q  ->  P(k) = q*36 + lane
                float* row = sAct + (m0 + sub * 8 + i) * RS;
                row[lane]       = w.x;
                row[36 + lane]  = w.y;
                row[72 + lane]  = w.z;
                row[108 + lane] = w.w;
            }
        }
        band_bar(band);

        // ---- GEMM1: acc = sAct[band] @ W1 ;  LDS.128 covers 2 k-chunks ----
        float acc[2][4][4];
#pragma unroll
        for (int i = 0; i < 2; i++)
#pragma unroll
            for (int j = 0; j < 4; j++)
#pragma unroll
                for (int r = 0; r < 4; r++) acc[i][j][r] = 0.f;

#pragma unroll
        for (int t = 0; t < 8; t++) {
            float4 alo[2], ahi[2];
#pragma unroll
            for (int i = 0; i < 2; i++) {
                const float* base = sAct + (m0 + i * 16 + g) * RS + cb + 4 * t;
                alo[i] = *reinterpret_cast<const float4*>(base);
                ahi[i] = *reinterpret_cast<const float4*>(base + 8 * RS);
            }
            float4 bw[4];
#pragma unroll
            for (int j = 0; j < 4; j++)
                bw[j] = *reinterpret_cast<const float4*>(sW1T + (n0 + j * 8 + g) * RS + cb + 4 * t);
#pragma unroll
            for (int i = 0; i < 2; i++)
#pragma unroll
                for (int j = 0; j < 4; j++) {
                    mma_tf32(acc[i][j],
                             __float_as_uint(alo[i].x), __float_as_uint(ahi[i].x),
                             __float_as_uint(alo[i].y), __float_as_uint(ahi[i].y),
                             __float_as_uint(bw[j].x),  __float_as_uint(bw[j].y));
                    mma_tf32(acc[i][j],
                             __float_as_uint(alo[i].z), __float_as_uint(ahi[i].z),
                             __float_as_uint(alo[i].w), __float_as_uint(ahi[i].w),
                             __float_as_uint(bw[j].z),  __float_as_uint(bw[j].w));
                }
        }
        band_bar(band);   // band done READING its sAct rows

        // ---- layer-1 epilogue: overwrite band rows (permuted positions) ----
#pragma unroll
        for (int i = 0; i < 2; i++)
#pragma unroll
            for (int j = 0; j < 4; j++) {
                int n1 = n0 + j * 8 + 2 * c;
                int p0 = permk(n1), p1 = permk(n1 + 1);
                float bb0 = sB1[n1], bb1 = sB1[n1 + 1];
                float* r0 = sAct + (m0 + i * 16 + g) * RS;
                float* r1 = r0 + 8 * RS;
                r0[p0] = tf32f(leaky(acc[i][j][0] + bb0));
                r0[p1] = tf32f(leaky(acc[i][j][1] + bb1));
                r1[p0] = tf32f(leaky(acc[i][j][2] + bb0));
                r1[p1] = tf32f(leaky(acc[i][j][3] + bb1));
            }
        band_bar(band);

        // ---- GEMM2: out[band] = leaky(sAct[band] @ W2 + b2), 32x16 tiles ----
        {
            float acc2[2][2][4];
#pragma unroll
            for (int i = 0; i < 2; i++)
#pragma unroll
                for (int j = 0; j < 2; j++)
#pragma unroll
                    for (int r = 0; r < 4; r++) acc2[i][j][r] = 0.f;

#pragma unroll
            for (int t = 0; t < 8; t++) {
                float4 alo[2], ahi[2];
#pragma unroll
                for (int i = 0; i < 2; i++) {
                    const float* base = sAct + (m0 + i * 16 + g) * RS + cb + 4 * t;
                    alo[i] = *reinterpret_cast<const float4*>(base);
                    ahi[i] = *reinterpret_cast<const float4*>(base + 8 * RS);
                }
                float4 bw[2];
#pragma unroll
                for (int j = 0; j < 2; j++)
                    bw[j] = *reinterpret_cast<const float4*>(sW2T + (n02 + j * 8 + g) * RS + cb + 4 * t);
#pragma unroll
                for (int i = 0; i < 2; i++)
#pragma unroll
                    for (int j = 0; j < 2; j++) {
                        mma_tf32(acc2[i][j],
                                 __float_as_uint(alo[i].x), __float_as_uint(ahi[i].x),
                                 __float_as_uint(alo[i].y), __float_as_uint(ahi[i].y),
                                 __float_as_uint(bw[j].x),  __float_as_uint(bw[j].y));
                        mma_tf32(acc2[i][j],
                                 __float_as_uint(alo[i].z), __float_as_uint(ahi[i].z),
                                 __float_as_uint(alo[i].w), __float_as_uint(ahi[i].w),
                                 __float_as_uint(bw[j].z),  __float_as_uint(bw[j].w));
                    }
            }

#pragma unroll
            for (int i = 0; i < 2; i++)
#pragma unroll
                for (int j = 0; j < 2; j++) {
                    int row = m0 + i * 16 + g;
                    int col = n02 + j * 8 + 2 * c;
                    if (e0 + row < n_edges) {
                        float2 v;
                        v.x = leaky(acc2[i][j][0] + sB2[col]);
                        v.y = leaky(acc2[i][j][1] + sB2[col + 1]);
                        *reinterpret_cast<float2*>(out + (size_t)(e0 + row) * OD + col) = v;
                    }
                    if (e0 + row + 8 < n_edges) {
                        float2 v;
                        v.x = leaky(acc2[i][j][2] + sB2[col]);
                        v.y = leaky(acc2[i][j][3] + sB2[col + 1]);
                        *reinterpret_cast<float2*>(out + (size_t)(e0 + row + 8) * OD + col) = v;
                    }
                }
        }
        band_bar(band);   // band's sAct reads done before next tile's gather
    }
}

// ---------------------------------------------------------------------------
// Launch. Inputs: x, edge_index(int32), W0, b0, W1, b1, W2, b2
// ---------------------------------------------------------------------------
extern "C" void kernel_launch(void* const* d_in, const int* in_sizes, int n_in,
                              void* d_out, int out_size)
{
    const float* x  = (const float*)d_in[0];
    const int*   ei = (const int*)d_in[1];
    const float* W0 = (const float*)d_in[2];
    const float* b0 = (const float*)d_in[3];
    const float* W1 = (const float*)d_in[4];
    const float* b1 = (const float*)d_in[5];
    const float* W2 = (const float*)d_in[6];
    const float* b2 = (const float*)d_in[7];
    float* out = (float*)d_out;

    const int n_nodes = in_sizes[0] / ND;
    const int n_edges = in_sizes[1] / 2;

    cudaFuncSetAttribute(edge_mlp, cudaFuncAttributeMaxDynamicSharedMemorySize, SMEM_BYTES);

    node_gemm<<<(n_nodes + 63) / 64, 256>>>(x, W0, n_nodes);
    edge_mlp<<<148, 512, SMEM_BYTES>>>(ei, W1, W2, b0, b1, b2, out, n_edges, n_nodes);
}

// round 11
// speedup vs baseline: 1.1680x; 1.1680x over previous
#include <cuda_runtime.h>

// ---------------------------------------------------------------------------
// EdgeAttrConstruct: out[e] = L(L(L((x[s]+x[d])@W0+b0)@W1+b1)@W2+b2), L=leaky(0.05)
// Factored: h0 = x@W0 per node; per edge: act1 = L(h0[s]+h0[d]+b0), then two
// TF32 mma.sync GEMMs per 192-edge tile. CTA = SIX independent 32-row band
// pipelines (4 warps each, named barriers). 768 threads -> 24 warps/SM.
// edge_index is int32 (JAX canonicalization).
// ---------------------------------------------------------------------------

#define SLOPE 0.05f

constexpr int ND = 64;
constexpr int HD = 128;
constexpr int OD = 64;

constexpr int TILE_E = 192;         // edges per tile (32 per band, 6 bands)
constexpr int SA = 132;             // act stride (==4 mod 32: conflict-free A-frag LDS)
constexpr int S1 = 136;             // W1 stride  (==8 mod 32: conflict-free B-frag LDS)
constexpr int S2 = 72;              // W2 stride  (==8 mod 32)
constexpr int NW1 = HD * S1;        // 17408 floats
constexpr int NW2 = HD * S2;        //  9216 floats
constexpr int NACT = TILE_E * SA;   // 25344 floats
constexpr int SMEM_FLOATS = NW1 + NW2 + NACT + 128 + 128 + 64;
constexpr int SMEM_BYTES = SMEM_FLOATS * 4;   // 209152 B  (< 227 KB cap)

__device__ float g_h0[(size_t)50000 * HD];

__device__ __forceinline__ float leaky(float v) { return v >= 0.f ? v : SLOPE * v; }

__device__ __forceinline__ unsigned tf32u(float x) {
    unsigned u;
    asm("cvt.rna.tf32.f32 %0, %1;" : "=r"(u) : "f"(x));
    return u;
}
__device__ __forceinline__ float tf32f(float x) { return __uint_as_float(tf32u(x)); }

__device__ __forceinline__ void mma_tf32(float* c, const unsigned* a, const unsigned* b) {
    asm volatile(
        "mma.sync.aligned.m16n8k8.row.col.f32.tf32.tf32.f32 "
        "{%0,%1,%2,%3}, {%4,%5,%6,%7}, {%8,%9}, {%0,%1,%2,%3};"
        : "+f"(c[0]), "+f"(c[1]), "+f"(c[2]), "+f"(c[3])
        : "r"(a[0]), "r"(a[1]), "r"(a[2]), "r"(a[3]), "r"(b[0]), "r"(b[1]));
}

__device__ __forceinline__ void band_bar(int band) {
    asm volatile("bar.sync %0, 128;" :: "r"(band + 1) : "memory");
}

// ---------------------------------------------------------------------------
// Kernel 1: g_h0 = x @ W0   (50000x64 @ 64x128)
// ---------------------------------------------------------------------------
__global__ __launch_bounds__(256) void node_gemm(
    const float* __restrict__ x, const float* __restrict__ W0, int n_nodes)
{
    __shared__ float sW[ND * HD];
    __shared__ float sX[64 * 68];

    const int tid = threadIdx.x;
    for (int i = tid; i < ND * HD; i += 256) sW[i] = W0[i];

    const int node0 = blockIdx.x * 64;
    for (int t = tid; t < 64 * 16; t += 256) {
        int r = t >> 4, q = t & 15;
        int node = node0 + r;
        float4 v = make_float4(0.f, 0.f, 0.f, 0.f);
        if (node < n_nodes) v = *reinterpret_cast<const float4*>(x + (size_t)node * ND + q * 4);
        *reinterpret_cast<float4*>(sX + r * 68 + q * 4) = v;
    }
    __syncthreads();

    const int tx = tid & 31, ty = tid >> 5;
    float acc[8][4];
#pragma unroll
    for (int i = 0; i < 8; i++)
#pragma unroll
        for (int j = 0; j < 4; j++) acc[i][j] = 0.f;

#pragma unroll 4
    for (int k = 0; k < ND; k++) {
        float w[4];
#pragma unroll
        for (int j = 0; j < 4; j++) w[j] = sW[k * HD + tx + 32 * j];
#pragma unroll
        for (int i = 0; i < 8; i++) {
            float xv = sX[(ty + 8 * i) * 68 + k];
#pragma unroll
            for (int j = 0; j < 4; j++) acc[i][j] = fmaf(xv, w[j], acc[i][j]);
        }
    }

#pragma unroll
    for (int i = 0; i < 8; i++) {
        int node = node0 + ty + 8 * i;
        if (node < n_nodes) {
#pragma unroll
            for (int j = 0; j < 4; j++)
                g_h0[(size_t)node * HD + tx + 32 * j] = acc[i][j];
        }
    }
}

// ---------------------------------------------------------------------------
// Kernel 2: persistent edge MLP. grid=148, 768 threads, 209 KB dyn smem.
// 6 bands x 4 warps. Per 192-edge tile, each band independently:
//   gather:  its 32 rows of sAct = tf32(leaky(h0[s]+h0[d]+b0))
//   GEMM1:   band rows @ W1 -> regs; epilogue overwrites band rows in place
//   GEMM2:   band rows @ W2 -> gmem (4 warps, 32x16 tiles)
// synchronized only with bar.sync(band+1, 128).
// ---------------------------------------------------------------------------
__global__ __launch_bounds__(768, 1) void edge_mlp(
    const int* __restrict__ ei,
    const float* __restrict__ W1, const float* __restrict__ W2,
    const float* __restrict__ b0, const float* __restrict__ b1,
    const float* __restrict__ b2,
    float* __restrict__ out, int n_edges, int n_nodes)
{
    extern __shared__ float sm[];
    float* sW1 = sm;                 // [128][136] tf32
    float* sW2 = sW1 + NW1;          // [128][72]  tf32
    float* sAct = sW2 + NW2;         // [192][132]
    float* sB0 = sAct + NACT;        // [128]
    float* sB1 = sB0 + 128;          // [128]
    float* sB2 = sB1 + 128;          // [64]

    const int tid = threadIdx.x;

    for (int i = tid; i < HD * HD; i += 768)
        sW1[(i >> 7) * S1 + (i & 127)] = tf32f(W1[i]);
    for (int i = tid; i < HD * OD; i += 768)
        sW2[(i >> 6) * S2 + (i & 63)] = tf32f(W2[i]);
    if (tid < 128) { sB0[tid] = b0[tid]; sB1[tid] = b1[tid]; }
    else if (tid >= 256 && tid < 320) sB2[tid - 256] = b2[tid - 256];
    __syncthreads();

    const int lane = tid & 31, wid = tid >> 5;
    const int g = lane >> 2, c = lane & 3;
    const int band = wid % 6;        // 0..5 : 32-row band, 4 warps each
    const int sub  = wid / 6;        // 0..3 : position within band
    const int m0  = band * 32;       // band row base in sAct
    const int n0  = sub * 32;        // GEMM1 n-tile base
    const int n02 = sub * 16;        // GEMM2 n-tile base

    const int n_tiles = (n_edges + TILE_E - 1) / TILE_E;
    for (int tile = blockIdx.x; tile < n_tiles; tile += gridDim.x) {
        const int e0 = tile * TILE_E;

        // ---- gather: this warp owns 8 rows [m0+sub*8, +8) of the band ----
        {
            const int e_base = e0 + m0 + sub * 8;
            // lanes 0-7 load src idx for rows 0..7, lanes 8-15 load dst idx
            int idx = 0;
            if (lane < 16) {
                int e = e_base + (lane & 7);
                if (e < n_edges)
                    idx = __ldg(ei + (lane < 8 ? 0 : (size_t)n_edges) + e);
            }
            idx = min(max(idx, 0), n_nodes - 1);
            float4 bb = *reinterpret_cast<const float4*>(sB0 + lane * 4);
#pragma unroll
            for (int i = 0; i < 8; i++) {
                int s = __shfl_sync(0xffffffffu, idx, i);
                int d = __shfl_sync(0xffffffffu, idx, i + 8);
                float4 w;
                if (e_base + i < n_edges) {
                    float4 va = *reinterpret_cast<const float4*>(&g_h0[(size_t)s * HD + lane * 4]);
                    float4 vb = *reinterpret_cast<const float4*>(&g_h0[(size_t)d * HD + lane * 4]);
                    w.x = tf32f(leaky(va.x + vb.x + bb.x));
                    w.y = tf32f(leaky(va.y + vb.y + bb.y));
                    w.z = tf32f(leaky(va.z + vb.z + bb.z));
                    w.w = tf32f(leaky(va.w + vb.w + bb.w));
                } else {
                    w = make_float4(0.f, 0.f, 0.f, 0.f);
                }
                *reinterpret_cast<float4*>(sAct + (m0 + sub * 8 + i) * SA + lane * 4) = w;
            }
        }
        band_bar(band);

        // ---- GEMM1 mainloop: acc = sAct[band] @ W1 ----
        float acc[2][4][4];
#pragma unroll
        for (int i = 0; i < 2; i++)
#pragma unroll
            for (int j = 0; j < 4; j++)
#pragma unroll
                for (int r = 0; r < 4; r++) acc[i][j][r] = 0.f;

#pragma unroll
        for (int k0 = 0; k0 < HD; k0 += 8) {
            unsigned a[2][4];
#pragma unroll
            for (int i = 0; i < 2; i++) {
                const float* Ab = sAct + (m0 + i * 16) * SA + k0;
                a[i][0] = __float_as_uint(Ab[g * SA + c]);
                a[i][1] = __float_as_uint(Ab[(g + 8) * SA + c]);
                a[i][2] = __float_as_uint(Ab[g * SA + c + 4]);
                a[i][3] = __float_as_uint(Ab[(g + 8) * SA + c + 4]);
            }
            unsigned bf[4][2];
#pragma unroll
            for (int j = 0; j < 4; j++) {
                const float* Bb = sW1 + (k0 + c) * S1 + n0 + j * 8 + g;
                bf[j][0] = __float_as_uint(Bb[0]);
                bf[j][1] = __float_as_uint(Bb[4 * S1]);
            }
#pragma unroll
            for (int i = 0; i < 2; i++)
#pragma unroll
                for (int j = 0; j < 4; j++) mma_tf32(acc[i][j], a[i], bf[j]);
        }
        band_bar(band);    // band done READING its sAct rows

        // ---- layer-1 epilogue: overwrite band rows in place ----
#pragma unroll
        for (int i = 0; i < 2; i++)
#pragma unroll
            for (int j = 0; j < 4; j++) {
                int row = m0 + i * 16 + g;
                int col = n0 + j * 8 + 2 * c;
                float2 v0, v1;
                v0.x = tf32f(leaky(acc[i][j][0] + sB1[col]));
                v0.y = tf32f(leaky(acc[i][j][1] + sB1[col + 1]));
                v1.x = tf32f(leaky(acc[i][j][2] + sB1[col]));
                v1.y = tf32f(leaky(acc[i][j][3] + sB1[col + 1]));
                *reinterpret_cast<float2*>(sAct + row * SA + col) = v0;
                *reinterpret_cast<float2*>(sAct + (row + 8) * SA + col) = v1;
            }
        band_bar(band);

        // ---- GEMM2: out[band] = leaky(sAct[band] @ W2 + b2), 32x16 tiles ----
        {
            float acc2[2][2][4];
#pragma unroll
            for (int i = 0; i < 2; i++)
#pragma unroll
                for (int j = 0; j < 2; j++)
#pragma unroll
                    for (int r = 0; r < 4; r++) acc2[i][j][r] = 0.f;

#pragma unroll
            for (int k0 = 0; k0 < HD; k0 += 8) {
                unsigned a[2][4];
#pragma unroll
                for (int i = 0; i < 2; i++) {
                    const float* Ab = sAct + (m0 + i * 16) * SA + k0;
                    a[i][0] = __float_as_uint(Ab[g * SA + c]);
                    a[i][1] = __float_as_uint(Ab[(g + 8) * SA + c]);
                    a[i][2] = __float_as_uint(Ab[g * SA + c + 4]);
                    a[i][3] = __float_as_uint(Ab[(g + 8) * SA + c + 4]);
                }
                unsigned bf[2][2];
#pragma unroll
                for (int j = 0; j < 2; j++) {
                    const float* Bb = sW2 + (k0 + c) * S2 + n02 + j * 8 + g;
                    bf[j][0] = __float_as_uint(Bb[0]);
                    bf[j][1] = __float_as_uint(Bb[4 * S2]);
                }
#pragma unroll
                for (int i = 0; i < 2; i++)
#pragma unroll
                    for (int j = 0; j < 2; j++) mma_tf32(acc2[i][j], a[i], bf[j]);
            }

#pragma unroll
            for (int i = 0; i < 2; i++)
#pragma unroll
                for (int j = 0; j < 2; j++) {
                    int row = m0 + i * 16 + g;
                    int col = n02 + j * 8 + 2 * c;
                    if (e0 + row < n_edges) {
                        float2 v;
                        v.x = leaky(acc2[i][j][0] + sB2[col]);
                        v.y = leaky(acc2[i][j][1] + sB2[col + 1]);
                        *reinterpret_cast<float2*>(out + (size_t)(e0 + row) * OD + col) = v;
                    }
                    if (e0 + row + 8 < n_edges) {
                        float2 v;
                        v.x = leaky(acc2[i][j][2] + sB2[col]);
                        v.y = leaky(acc2[i][j][3] + sB2[col + 1]);
                        *reinterpret_cast<float2*>(out + (size_t)(e0 + row + 8) * OD + col) = v;
                    }
                }
        }
        band_bar(band);    // band's sAct reads done before next tile's gather
    }
}

// ---------------------------------------------------------------------------
// Launch. Inputs: x, edge_index(int32), W0, b0, W1, b1, W2, b2
// ---------------------------------------------------------------------------
extern "C" void kernel_launch(void* const* d_in, const int* in_sizes, int n_in,
                              void* d_out, int out_size)
{
    const float* x  = (const float*)d_in[0];
    const int*   ei = (const int*)d_in[1];
    const float* W0 = (const float*)d_in[2];
    const float* b0 = (const float*)d_in[3];
    const float* W1 = (const float*)d_in[4];
    const float* b1 = (const float*)d_in[5];
    const float* W2 = (const float*)d_in[6];
    const float* b2 = (const float*)d_in[7];
    float* out = (float*)d_out;

    const int n_nodes = in_sizes[0] / ND;
    const int n_edges = in_sizes[1] / 2;

    cudaFuncSetAttribute(edge_mlp, cudaFuncAttributeMaxDynamicSharedMemorySize, SMEM_BYTES);

    node_gemm<<<(n_nodes + 63) / 64, 256>>>(x, W0, n_nodes);
    edge_mlp<<<148, 768, SMEM_BYTES>>>(ei, W1, W2, b0, b1, b2, out, n_edges, n_nodes);
}

// round 17
// speedup vs baseline: 1.2266x; 1.0501x over previous
#include <cuda_runtime.h>

// ---------------------------------------------------------------------------
// EdgeAttrConstruct: out[e] = L(L(L((x[s]+x[d])@W0+b0)@W1+b1)@W2+b2), L=leaky(0.05)
// Factored: h0 = x@W0 per node (TF32 mma); per edge: act1 = L(h0[s]+h0[d]+b0),
// then two TF32 mma GEMMs per 224-edge tile. CTA = SEVEN independent 32-row
// band pipelines (4 warps each, named barriers). 896 threads -> 28 warps/SM.
// edge_index is int32 (JAX canonicalization).
// ---------------------------------------------------------------------------

#define SLOPE 0.05f

constexpr int ND = 64;
constexpr int HD = 128;
constexpr int OD = 64;

constexpr int NBANDS = 7;
constexpr int TILE_E = 32 * NBANDS; // 224 edges per tile
constexpr int SA = 132;             // act stride (==4 mod 32: conflict-free A-frag LDS)
constexpr int S1 = 136;             // W1 stride  (==8 mod 32: conflict-free B-frag LDS)
constexpr int S2 = 72;              // W2 stride  (==8 mod 32)
constexpr int NW1 = HD * S1;        // 17408 floats
constexpr int NW2 = HD * S2;        //  9216 floats
constexpr int NACT = TILE_E * SA;   // 29568 floats
constexpr int SMEM_FLOATS = NW1 + NW2 + NACT + 128 + 128 + 64;
constexpr int SMEM_BYTES = SMEM_FLOATS * 4;   // 226048 B (< 227 KB cap)

__device__ float g_h0[(size_t)50000 * HD];

__device__ __forceinline__ float leaky(float v) { return v >= 0.f ? v : SLOPE * v; }

__device__ __forceinline__ unsigned tf32u(float x) {
    unsigned u;
    asm("cvt.rna.tf32.f32 %0, %1;" : "=r"(u) : "f"(x));
    return u;
}
__device__ __forceinline__ float tf32f(float x) { return __uint_as_float(tf32u(x)); }

__device__ __forceinline__ void mma_tf32(float* c, const unsigned* a, const unsigned* b) {
    asm volatile(
        "mma.sync.aligned.m16n8k8.row.col.f32.tf32.tf32.f32 "
        "{%0,%1,%2,%3}, {%4,%5,%6,%7}, {%8,%9}, {%0,%1,%2,%3};"
        : "+f"(c[0]), "+f"(c[1]), "+f"(c[2]), "+f"(c[3])
        : "r"(a[0]), "r"(a[1]), "r"(a[2]), "r"(a[3]), "r"(b[0]), "r"(b[1]));
}

__device__ __forceinline__ void band_bar(int band) {
    asm volatile("bar.sync %0, 128;" :: "r"(band + 1) : "memory");
}

// ---------------------------------------------------------------------------
// Kernel 1: g_h0 = x @ W0   (50000x64 @ 64x128), TF32 tensor-core.
// Block: 256 threads (8 warps, 2x4 grid of 32x32 warp tiles), 64 nodes.
// ---------------------------------------------------------------------------
__global__ __launch_bounds__(256) void node_gemm(
    const float* __restrict__ x, const float* __restrict__ W0, int n_nodes)
{
    __shared__ float sX[64 * 68];    // x tile, tf32-rounded, stride 68 (==4 mod 32)
    __shared__ float sW[ND * S1];    // W0 tf32-rounded, stride 136 (==8 mod 32)

    const int tid = threadIdx.x;
    for (int i = tid; i < ND * HD; i += 256)
        sW[(i >> 7) * S1 + (i & 127)] = tf32f(W0[i]);

    const int node0 = blockIdx.x * 64;
    for (int t = tid; t < 64 * 16; t += 256) {   // float4 units
        int r = t >> 4, q = t & 15;
        int node = node0 + r;
        float4 v = make_float4(0.f, 0.f, 0.f, 0.f);
        if (node < n_nodes) {
            v = *reinterpret_cast<const float4*>(x + (size_t)node * ND + q * 4);
            v.x = tf32f(v.x); v.y = tf32f(v.y); v.z = tf32f(v.z); v.w = tf32f(v.w);
        }
        *reinterpret_cast<float4*>(sX + r * 68 + q * 4) = v;
    }
    __syncthreads();

    const int lane = tid & 31, wid = tid >> 5;
    const int g = lane >> 2, c = lane & 3;
    const int m0 = (wid & 1) * 32;
    const int n0 = (wid >> 1) * 32;

    float acc[2][4][4];
#pragma unroll
    for (int i = 0; i < 2; i++)
#pragma unroll
        for (int j = 0; j < 4; j++)
#pragma unroll
            for (int r = 0; r < 4; r++) acc[i][j][r] = 0.f;

#pragma unroll
    for (int k0 = 0; k0 < ND; k0 += 8) {
        unsigned a[2][4];
#pragma unroll
        for (int i = 0; i < 2; i++) {
            const float* Ab = sX + (m0 + i * 16) * 68 + k0;
            a[i][0] = __float_as_uint(Ab[g * 68 + c]);
            a[i][1] = __float_as_uint(Ab[(g + 8) * 68 + c]);
            a[i][2] = __float_as_uint(Ab[g * 68 + c + 4]);
            a[i][3] = __float_as_uint(Ab[(g + 8) * 68 + c + 4]);
        }
        unsigned bf[4][2];
#pragma unroll
        for (int j = 0; j < 4; j++) {
            const float* Bb = sW + (k0 + c) * S1 + n0 + j * 8 + g;
            bf[j][0] = __float_as_uint(Bb[0]);
            bf[j][1] = __float_as_uint(Bb[4 * S1]);
        }
#pragma unroll
        for (int i = 0; i < 2; i++)
#pragma unroll
            for (int j = 0; j < 4; j++) mma_tf32(acc[i][j], a[i], bf[j]);
    }

#pragma unroll
    for (int i = 0; i < 2; i++)
#pragma unroll
        for (int j = 0; j < 4; j++) {
            int row = m0 + i * 16 + g;
            int col = n0 + j * 8 + 2 * c;
            if (node0 + row < n_nodes) {
                float2 v = make_float2(acc[i][j][0], acc[i][j][1]);
                *reinterpret_cast<float2*>(&g_h0[(size_t)(node0 + row) * HD + col]) = v;
            }
            if (node0 + row + 8 < n_nodes) {
                float2 v = make_float2(acc[i][j][2], acc[i][j][3]);
                *reinterpret_cast<float2*>(&g_h0[(size_t)(node0 + row + 8) * HD + col]) = v;
            }
        }
}

// ---------------------------------------------------------------------------
// Kernel 2: persistent edge MLP. grid=148, 896 threads, 226 KB dyn smem.
// 7 bands x 4 warps. Per 224-edge tile, each band independently:
//   gather:  its 32 rows of sAct = tf32(leaky(h0[s]+h0[d]+b0))
//   GEMM1:   band rows @ W1 -> regs; epilogue overwrites band rows in place
//   GEMM2:   band rows @ W2 -> gmem (4 warps, 32x16 tiles)
// synchronized only with bar.sync(band+1, 128).
// ---------------------------------------------------------------------------
__global__ __launch_bounds__(896, 1) void edge_mlp(
    const int* __restrict__ ei,
    const float* __restrict__ W1, const float* __restrict__ W2,
    const float* __restrict__ b0, const float* __restrict__ b1,
    const float* __restrict__ b2,
    float* __restrict__ out, int n_edges, int n_nodes)
{
    extern __shared__ float sm[];
    float* sW1 = sm;                 // [128][136] tf32
    float* sW2 = sW1 + NW1;          // [128][72]  tf32
    float* sAct = sW2 + NW2;         // [224][132]
    float* sB0 = sAct + NACT;        // [128]
    float* sB1 = sB0 + 128;          // [128]
    float* sB2 = sB1 + 128;          // [64]

    const int tid = threadIdx.x;

    for (int i = tid; i < HD * HD; i += 896)
        sW1[(i >> 7) * S1 + (i & 127)] = tf32f(W1[i]);
    for (int i = tid; i < HD * OD; i += 896)
        sW2[(i >> 6) * S2 + (i & 63)] = tf32f(W2[i]);
    if (tid < 128) { sB0[tid] = b0[tid]; sB1[tid] = b1[tid]; }
    else if (tid >= 256 && tid < 320) sB2[tid - 256] = b2[tid - 256];
    __syncthreads();

    const int lane = tid & 31, wid = tid >> 5;
    const int g = lane >> 2, c = lane & 3;
    const int band = wid % NBANDS;   // 0..6 : 32-row band, 4 warps each
    const int sub  = wid / NBANDS;   // 0..3 : position within band
    const int m0  = band * 32;       // band row base in sAct
    const int n0  = sub * 32;        // GEMM1 n-tile base
    const int n02 = sub * 16;        // GEMM2 n-tile base

    const int n_tiles = (n_edges + TILE_E - 1) / TILE_E;
    for (int tile = blockIdx.x; tile < n_tiles; tile += gridDim.x) {
        const int e0 = tile * TILE_E;

        // ---- gather: this warp owns 8 rows [m0+sub*8, +8) of the band ----
        {
            const int e_base = e0 + m0 + sub * 8;
            int idx = 0;
            if (lane < 16) {
                int e = e_base + (lane & 7);
                if (e < n_edges)
                    idx = __ldg(ei + (lane < 8 ? 0 : (size_t)n_edges) + e);
            }
            idx = min(max(idx, 0), n_nodes - 1);
            float4 bb = *reinterpret_cast<const float4*>(sB0 + lane * 4);
#pragma unroll
            for (int i = 0; i < 8; i++) {
                int s = __shfl_sync(0xffffffffu, idx, i);
                int d = __shfl_sync(0xffffffffu, idx, i + 8);
                float4 w;
                if (e_base + i < n_edges) {
                    float4 va = *reinterpret_cast<const float4*>(&g_h0[(size_t)s * HD + lane * 4]);
                    float4 vb = *reinterpret_cast<const float4*>(&g_h0[(size_t)d * HD + lane * 4]);
                    w.x = tf32f(leaky(va.x + vb.x + bb.x));
                    w.y = tf32f(leaky(va.y + vb.y + bb.y));
                    w.z = tf32f(leaky(va.z + vb.z + bb.z));
                    w.w = tf32f(leaky(va.w + vb.w + bb.w));
                } else {
                    w = make_float4(0.f, 0.f, 0.f, 0.f);
                }
                *reinterpret_cast<float4*>(sAct + (m0 + sub * 8 + i) * SA + lane * 4) = w;
            }
        }
        band_bar(band);

        // ---- GEMM1 mainloop: acc = sAct[band] @ W1 ----
        float acc[2][4][4];
#pragma unroll
        for (int i = 0; i < 2; i++)
#pragma unroll
            for (int j = 0; j < 4; j++)
#pragma unroll
                for (int r = 0; r < 4; r++) acc[i][j][r] = 0.f;

#pragma unroll
        for (int k0 = 0; k0 < HD; k0 += 8) {
            unsigned a[2][4];
#pragma unroll
            for (int i = 0; i < 2; i++) {
                const float* Ab = sAct + (m0 + i * 16) * SA + k0;
                a[i][0] = __float_as_uint(Ab[g * SA + c]);
                a[i][1] = __float_as_uint(Ab[(g + 8) * SA + c]);
                a[i][2] = __float_as_uint(Ab[g * SA + c + 4]);
                a[i][3] = __float_as_uint(Ab[(g + 8) * SA + c + 4]);
            }
            unsigned bf[4][2];
#pragma unroll
            for (int j = 0; j < 4; j++) {
                const float* Bb = sW1 + (k0 + c) * S1 + n0 + j * 8 + g;
                bf[j][0] = __float_as_uint(Bb[0]);
                bf[j][1] = __float_as_uint(Bb[4 * S1]);
            }
#pragma unroll
            for (int i = 0; i < 2; i++)
#pragma unroll
                for (int j = 0; j < 4; j++) mma_tf32(acc[i][j], a[i], bf[j]);
        }
        band_bar(band);    // band done READING its sAct rows

        // ---- layer-1 epilogue: overwrite band rows in place ----
#pragma unroll
        for (int i = 0; i < 2; i++)
#pragma unroll
            for (int j = 0; j < 4; j++) {
                int row = m0 + i * 16 + g;
                int col = n0 + j * 8 + 2 * c;
                float2 v0, v1;
                v0.x = tf32f(leaky(acc[i][j][0] + sB1[col]));
                v0.y = tf32f(leaky(acc[i][j][1] + sB1[col + 1]));
                v1.x = tf32f(leaky(acc[i][j][2] + sB1[col]));
                v1.y = tf32f(leaky(acc[i][j][3] + sB1[col + 1]));
                *reinterpret_cast<float2*>(sAct + row * SA + col) = v0;
                *reinterpret_cast<float2*>(sAct + (row + 8) * SA + col) = v1;
            }
        band_bar(band);

        // ---- GEMM2: out[band] = leaky(sAct[band] @ W2 + b2), 32x16 tiles ----
        {
            float acc2[2][2][4];
#pragma unroll
            for (int i = 0; i < 2; i++)
#pragma unroll
                for (int j = 0; j < 2; j++)
#pragma unroll
                    for (int r = 0; r < 4; r++) acc2[i][j][r] = 0.f;

#pragma unroll
            for (int k0 = 0; k0 < HD; k0 += 8) {
                unsigned a[2][4];
#pragma unroll
                for (int i = 0; i < 2; i++) {
                    const float* Ab = sAct + (m0 + i * 16) * SA + k0;
                    a[i][0] = __float_as_uint(Ab[g * SA + c]);
                    a[i][1] = __float_as_uint(Ab[(g + 8) * SA + c]);
                    a[i][2] = __float_as_uint(Ab[g * SA + c + 4]);
                    a[i][3] = __float_as_uint(Ab[(g + 8) * SA + c + 4]);
                }
                unsigned bf[2][2];
#pragma unroll
                for (int j = 0; j < 2; j++) {
                    const float* Bb = sW2 + (k0 + c) * S2 + n02 + j * 8 + g;
                    bf[j][0] = __float_as_uint(Bb[0]);
                    bf[j][1] = __float_as_uint(Bb[4 * S2]);
                }
#pragma unroll
                for (int i = 0; i < 2; i++)
#pragma unroll
                    for (int j = 0; j < 2; j++) mma_tf32(acc2[i][j], a[i], bf[j]);
            }

#pragma unroll
            for (int i = 0; i < 2; i++)
#pragma unroll
                for (int j = 0; j < 2; j++) {
                    int row = m0 + i * 16 + g;
                    int col = n02 + j * 8 + 2 * c;
                    if (e0 + row < n_edges) {
                        float2 v;
                        v.x = leaky(acc2[i][j][0] + sB2[col]);
                        v.y = leaky(acc2[i][j][1] + sB2[col + 1]);
                        *reinterpret_cast<float2*>(out + (size_t)(e0 + row) * OD + col) = v;
                    }
                    if (e0 + row + 8 < n_edges) {
                        float2 v;
                        v.x = leaky(acc2[i][j][2] + sB2[col]);
                        v.y = leaky(acc2[i][j][3] + sB2[col + 1]);
                        *reinterpret_cast<float2*>(out + (size_t)(e0 + row + 8) * OD + col) = v;
                    }
                }
        }
        band_bar(band);    // band's sAct reads done before next tile's gather
    }
}

// ---------------------------------------------------------------------------
// Launch. Inputs: x, edge_index(int32), W0, b0, W1, b1, W2, b2
// ---------------------------------------------------------------------------
extern "C" void kernel_launch(void* const* d_in, const int* in_sizes, int n_in,
                              void* d_out, int out_size)
{
    const float* x  = (const float*)d_in[0];
    const int*   ei = (const int*)d_in[1];
    const float* W0 = (const float*)d_in[2];
    const float* b0 = (const float*)d_in[3];
    const float* W1 = (const float*)d_in[4];
    const float* b1 = (const float*)d_in[5];
    const float* W2 = (const float*)d_in[6];
    const float* b2 = (const float*)d_in[7];
    float* out = (float*)d_out;

    const int n_nodes = in_sizes[0] / ND;
    const int n_edges = in_sizes[1] / 2;

    cudaFuncSetAttribute(edge_mlp, cudaFuncAttributeMaxDynamicSharedMemorySize, SMEM_BYTES);

    node_gemm<<<(n_nodes + 63) / 64, 256>>>(x, W0, n_nodes);
    edge_mlp<<<148, 896, SMEM_BYTES>>>(ei, W1, W2, b0, b1, b2, out, n_edges, n_nodes);
}